// round 5
// baseline (speedup 1.0000x reference)
#include <cuda_runtime.h>

// Problem shapes (fixed by the dataset)
#define BSZ  8
#define ENL  512   // encoder length
#define DEL  64    // decoder length
#define EDIM 512   // embedding
#define UDIM 512   // units
#define TDIM 100   // topics
#define STRIP 8    // strip depth in fused kernel (8 x float2 = 16 values)

// Scratch (no cudaMalloc allowed)
__device__ float g_aeT[BSZ * UDIM * ENL];   // att_en transposed: [b][u][i]  (8 MB)
__device__ float g_c  [BSZ * DEL * UDIM];   // att_de + topic bias: [b][j][u] (1 MB)

typedef unsigned long long ull;

__device__ __forceinline__ float tanh_fast(float x) {
    float y;
    asm("tanh.approx.f32 %0, %1;" : "=f"(y) : "f"(x));
    return y;
}
__device__ __forceinline__ ull pack2(float x, float y) {
    ull r; asm("mov.b64 %0, {%1, %2};" : "=l"(r) : "f"(x), "f"(y)); return r;
}
__device__ __forceinline__ ull fma2(ull a, ull b, ull c) {
    ull d; asm("fma.rn.f32x2 %0, %1, %2, %3;" : "=l"(d) : "l"(a), "l"(b), "l"(c));
    return d;
}

// ---------------------------------------------------------------------------
// Kernel 1: g_aeT[b][u][i] = sum_e en[b][i][e] * w_en[e][u]
// 64(i) x 128(u) tile, BK=16, 256 threads, 8(u)x4(i) microtile, f32x2 FMAs,
// double-buffered smem with register prefetch. grid = 8x4x8 = 256 blocks.
// ---------------------------------------------------------------------------
__global__ void __launch_bounds__(256, 2) k_gemm_aeT(
    const float* __restrict__ en, const float* __restrict__ w_en)
{
    const int b  = blockIdx.z;
    const int u0 = blockIdx.y * 128;
    const int i0 = blockIdx.x * 64;

    __shared__ float As[2][16][128];  // [e][u] (reads broadcast across warp)
    __shared__ float Bs[2][16][68];   // [e][i] (padded)

    const int tid = threadIdx.x;
    const int tx = tid & 15;          // i micro index (4 i's)
    const int ty = tid >> 4;          // u micro index (8 u's)

    // A-load: 128 u x 2 e per pass, 8 passes
    const int ua = tid & 127;
    const int ea = tid >> 7;
    // B-load: 16 e x 16 i per pass, 4 passes
    const int eb = tid & 15;
    const int ib = tid >> 4;

    const float* pa = w_en + (size_t)ea * UDIM + u0 + ua;
    const float* pb = en + (size_t)b * ENL * EDIM + (size_t)(i0 + ib) * EDIM + eb;

    ull acc[8][2] = {};

    // Prologue: tile 0 -> smem[0]
    #pragma unroll
    for (int p = 0; p < 8; p++)
        As[0][ea + 2 * p][ua] = pa[(size_t)(2 * p) * UDIM];
    #pragma unroll
    for (int p = 0; p < 4; p++)
        Bs[0][eb][ib + 16 * p] = pb[(size_t)(16 * p) * EDIM];
    __syncthreads();

    int s = 0;
    for (int t = 0; t < 32; t++) {
        float ra[8], rb[4];
        if (t < 31) {
            const float* qa = pa + (size_t)(t + 1) * 16 * UDIM;
            const float* qb = pb + (t + 1) * 16;
            #pragma unroll
            for (int p = 0; p < 8; p++) ra[p] = qa[(size_t)(2 * p) * UDIM];
            #pragma unroll
            for (int p = 0; p < 4; p++) rb[p] = qb[(size_t)(16 * p) * EDIM];
        }
        #pragma unroll
        for (int k = 0; k < 16; k++) {
            const float4 a0 = *(const float4*)&As[s][k][ty * 8];
            const float4 a1 = *(const float4*)&As[s][k][ty * 8 + 4];
            const ull b01 = *(const ull*)&Bs[s][k][tx * 4];
            const ull b23 = *(const ull*)&Bs[s][k][tx * 4 + 2];
            ull p0 = pack2(a0.x, a0.x), p1 = pack2(a0.y, a0.y);
            ull p2 = pack2(a0.z, a0.z), p3 = pack2(a0.w, a0.w);
            ull p4 = pack2(a1.x, a1.x), p5 = pack2(a1.y, a1.y);
            ull p6 = pack2(a1.z, a1.z), p7 = pack2(a1.w, a1.w);
            acc[0][0]=fma2(p0,b01,acc[0][0]); acc[0][1]=fma2(p0,b23,acc[0][1]);
            acc[1][0]=fma2(p1,b01,acc[1][0]); acc[1][1]=fma2(p1,b23,acc[1][1]);
            acc[2][0]=fma2(p2,b01,acc[2][0]); acc[2][1]=fma2(p2,b23,acc[2][1]);
            acc[3][0]=fma2(p3,b01,acc[3][0]); acc[3][1]=fma2(p3,b23,acc[3][1]);
            acc[4][0]=fma2(p4,b01,acc[4][0]); acc[4][1]=fma2(p4,b23,acc[4][1]);
            acc[5][0]=fma2(p5,b01,acc[5][0]); acc[5][1]=fma2(p5,b23,acc[5][1]);
            acc[6][0]=fma2(p6,b01,acc[6][0]); acc[6][1]=fma2(p6,b23,acc[6][1]);
            acc[7][0]=fma2(p7,b01,acc[7][0]); acc[7][1]=fma2(p7,b23,acc[7][1]);
        }
        if (t < 31) {
            #pragma unroll
            for (int p = 0; p < 8; p++) As[s ^ 1][ea + 2 * p][ua] = ra[p];
            #pragma unroll
            for (int p = 0; p < 4; p++) Bs[s ^ 1][eb][ib + 16 * p] = rb[p];
        }
        __syncthreads();
        s ^= 1;
    }

    float* outp = g_aeT + (size_t)b * UDIM * ENL
                + (size_t)(u0 + ty * 8) * ENL + i0 + tx * 4;
    #pragma unroll
    for (int q = 0; q < 8; q++) {
        ull* row = (ull*)(outp + (size_t)q * ENL);
        row[0] = acc[q][0]; row[1] = acc[q][1];
    }
}

// ---------------------------------------------------------------------------
// Kernel 2: g_c[b][j][u] = sum_e de[b][j][e] * w_de[e][u] + tw[b][u]
// ---------------------------------------------------------------------------
__global__ void __launch_bounds__(256) k_c(
    const float* __restrict__ de, const float* __restrict__ w_de,
    const float* __restrict__ topics, const float* __restrict__ wt)
{
    const int b  = blockIdx.y;
    const int u0 = blockIdx.x * 64;
    __shared__ float As[16][68];  // [e][j]
    __shared__ float Bs[16][68];  // [e][u]
    __shared__ float tws[64];
    const float* deb = de + (size_t)b * DEL * EDIM;
    const int tid = threadIdx.x;
    const int tj = tid & 15;
    const int tu = tid >> 4;
    ull acc2[4][2] = {};

    if (tid < 64) {
        float acc = 0.f;
        const float* wr = wt + (size_t)(u0 + tid) * TDIM;
        const float* tp = topics + b * TDIM;
        #pragma unroll 4
        for (int t = 0; t < TDIM; t++) acc = fmaf(tp[t], wr[t], acc);
        tws[tid] = acc;
    }

    for (int e0 = 0; e0 < EDIM; e0 += 16) {
        #pragma unroll
        for (int r = 0; r < 4; r++) {
            int l = tid + 256 * r;
            int e = l & 15, j = l >> 4;
            As[e][j] = deb[(size_t)j * EDIM + e0 + e];
        }
        #pragma unroll
        for (int r = 0; r < 4; r++) {
            int l = tid + 256 * r;
            int e = l >> 6, uu = l & 63;
            Bs[e][uu] = w_de[(size_t)(e0 + e) * UDIM + u0 + uu];
        }
        __syncthreads();
        #pragma unroll
        for (int k = 0; k < 16; k++) {
            const float4 av = *(const float4*)&As[k][tj * 4];
            const ull b01 = *(const ull*)&Bs[k][tu * 4];
            const ull b23 = *(const ull*)&Bs[k][tu * 4 + 2];
            ull pa0 = pack2(av.x, av.x), pa1 = pack2(av.y, av.y);
            ull pa2 = pack2(av.z, av.z), pa3 = pack2(av.w, av.w);
            acc2[0][0] = fma2(pa0, b01, acc2[0][0]); acc2[0][1] = fma2(pa0, b23, acc2[0][1]);
            acc2[1][0] = fma2(pa1, b01, acc2[1][0]); acc2[1][1] = fma2(pa1, b23, acc2[1][1]);
            acc2[2][0] = fma2(pa2, b01, acc2[2][0]); acc2[2][1] = fma2(pa2, b23, acc2[2][1]);
            acc2[3][0] = fma2(pa3, b01, acc2[3][0]); acc2[3][1] = fma2(pa3, b23, acc2[3][1]);
        }
        __syncthreads();
    }
    #pragma unroll
    for (int r = 0; r < 4; r++) {
        float2 v01, v23;
        asm("mov.b64 {%0, %1}, %2;" : "=f"(v01.x), "=f"(v01.y) : "l"(acc2[r][0]));
        asm("mov.b64 {%0, %1}, %2;" : "=f"(v23.x), "=f"(v23.y) : "l"(acc2[r][1]));
        int j = tj * 4 + r;
        float* row = g_c + ((size_t)b * DEL + j) * UDIM + u0 + tu * 4;
        row[0] = v01.x + tws[tu * 4 + 0];
        row[1] = v01.y + tws[tu * 4 + 1];
        row[2] = v23.x + tws[tu * 4 + 2];
        row[3] = v23.y + tws[tu * 4 + 3];
    }
}

// ---------------------------------------------------------------------------
// Kernel 3 (fused attention): block = (b, j0..j0+1), 256 threads,
// thread t owns encoder positions i = 2t, 2t+1 (float2 loads).
// ---------------------------------------------------------------------------
__global__ void __launch_bounds__(256) k_attn(
    const float* __restrict__ en, const float* __restrict__ de,
    const float* __restrict__ nu, float* __restrict__ out)
{
    const int b  = blockIdx.y;
    const int j0 = blockIdx.x * 2;
    const int t  = threadIdx.x;

    __shared__ float4 css[UDIM];    // (c[j0][u], c[j0+1][u], nu[u], 0)
    __shared__ float2 red2[8];
    __shared__ float2 alph[ENL];    // per i: (alpha_j0, alpha_j1)

    const float* cb = g_c + ((size_t)b * DEL + j0) * UDIM;
    css[t]       = make_float4(cb[t],       cb[UDIM + t],       nu[t],       0.f);
    css[t + 256] = make_float4(cb[t + 256], cb[UDIM + t + 256], nu[t + 256], 0.f);
    __syncthreads();

    // Phase 1: mu for i = 2t, 2t+1 and j = j0, j0+1
    const float* ae = g_aeT + (size_t)b * UDIM * ENL + 2 * t;
    float m00 = 0.f, m01 = 0.f, m10 = 0.f, m11 = 0.f;  // m[j][i]
    for (int u0 = 0; u0 < UDIM; u0 += STRIP) {
        float2 av[STRIP];
        #pragma unroll
        for (int k = 0; k < STRIP; k++)
            av[k] = __ldg((const float2*)(ae + (size_t)(u0 + k) * ENL));
        #pragma unroll
        for (int k = 0; k < STRIP; k++) {
            float4 c4 = css[u0 + k];
            m00 = fmaf(c4.z, tanh_fast(av[k].x + c4.x), m00);
            m01 = fmaf(c4.z, tanh_fast(av[k].y + c4.x), m01);
            m10 = fmaf(c4.z, tanh_fast(av[k].x + c4.y), m10);
            m11 = fmaf(c4.z, tanh_fast(av[k].y + c4.y), m11);
        }
    }

    const int wid = t >> 5, lane = t & 31;

    // Block max over i (per j)
    float2 r = make_float2(fmaxf(m00, m01), fmaxf(m10, m11));
    #pragma unroll
    for (int o = 16; o; o >>= 1) {
        r.x = fmaxf(r.x, __shfl_xor_sync(0xffffffffu, r.x, o));
        r.y = fmaxf(r.y, __shfl_xor_sync(0xffffffffu, r.y, o));
    }
    if (lane == 0) red2[wid] = r;
    __syncthreads();
    float2 M = red2[0];
    #pragma unroll
    for (int w = 1; w < 8; w++) {
        float2 q = red2[w];
        M.x = fmaxf(M.x, q.x); M.y = fmaxf(M.y, q.y);
    }
    __syncthreads();  // before reusing red2

    float e00 = __expf(m00 - M.x);
    float e01 = __expf(m01 - M.x);
    float e10 = __expf(m10 - M.y);
    float e11 = __expf(m11 - M.y);

    // Block sum over i (per j)
    float2 s = make_float2(e00 + e01, e10 + e11);
    #pragma unroll
    for (int o = 16; o; o >>= 1) {
        s.x += __shfl_xor_sync(0xffffffffu, s.x, o);
        s.y += __shfl_xor_sync(0xffffffffu, s.y, o);
    }
    if (lane == 0) red2[wid] = s;
    __syncthreads();
    float2 S = red2[0];
    #pragma unroll
    for (int w = 1; w < 8; w++) {
        float2 q = red2[w];
        S.x += q.x; S.y += q.y;
    }

    float inv0 = 1.f / S.x, inv1 = 1.f / S.y;
    float a00 = e00 * inv0, a01 = e01 * inv0;
    float a10 = e10 * inv1, a11 = e11 * inv1;
    alph[2 * t]     = make_float2(a00, a10);
    alph[2 * t + 1] = make_float2(a01, a11);

    // Output layout (flat tuple): [output | alphas | p_gen]
    float* alphas_out = out + BSZ * DEL * ENL;
    float* pgen_out   = out + 2 * BSZ * DEL * ENL;
    const int base = ((b * DEL + j0) * ENL) + 2 * t;
    *(float2*)(alphas_out + base      ) = make_float2(a00, a01);
    *(float2*)(alphas_out + base + ENL) = make_float2(a10, a11);
    *(float2*)(pgen_out + base      ) =
        make_float2(1.f / (1.f + __expf(-m00)), 1.f / (1.f + __expf(-m01)));
    *(float2*)(pgen_out + base + ENL) =
        make_float2(1.f / (1.f + __expf(-m10)), 1.f / (1.f + __expf(-m11)));
    __syncthreads();

    // Phase 2: sum_en[j][e] = sum_i alphas[j][i] * en[b][i][e], e = 2t, 2t+1
    float2 s0 = make_float2(0.f, 0.f), s1 = make_float2(0.f, 0.f);
    const float* enb = en + (size_t)b * ENL * EDIM + 2 * t;
    for (int i0 = 0; i0 < ENL; i0 += STRIP) {
        float2 ev[STRIP];
        #pragma unroll
        for (int k = 0; k < STRIP; k++)
            ev[k] = __ldg((const float2*)(enb + (size_t)(i0 + k) * EDIM));
        #pragma unroll
        for (int k = 0; k < STRIP; k++) {
            float2 av = alph[i0 + k];
            s0.x = fmaf(av.x, ev[k].x, s0.x);
            s0.y = fmaf(av.x, ev[k].y, s0.y);
            s1.x = fmaf(av.y, ev[k].x, s1.x);
            s1.y = fmaf(av.y, ev[k].y, s1.y);
        }
    }
    const int ob = ((b * DEL + j0) * EDIM) + 2 * t;
    float2 d0 = *(const float2*)(de + ob);
    float2 d1 = *(const float2*)(de + ob + EDIM);
    *(float2*)(out + ob       ) = make_float2(d0.x + s0.x, d0.y + s0.y);
    *(float2*)(out + ob + EDIM) = make_float2(d1.x + s1.x, d1.y + s1.y);
}

// ---------------------------------------------------------------------------
extern "C" void kernel_launch(void* const* d_in, const int* in_sizes, int n_in,
                              void* d_out, int out_size)
{
    const float* en     = (const float*)d_in[0];
    const float* de     = (const float*)d_in[1];
    const float* topics = (const float*)d_in[2];
    const float* w_en   = (const float*)d_in[3];
    const float* w_de   = (const float*)d_in[4];
    const float* nu     = (const float*)d_in[5];
    const float* wt     = (const float*)d_in[6];
    float* out = (float*)d_out;

    k_gemm_aeT<<<dim3(ENL / 64, UDIM / 128, BSZ), 256>>>(en, w_en);
    k_c<<<dim3(UDIM / 64, BSZ), 256>>>(de, w_de, topics, wt);
    k_attn<<<dim3(DEL / 2, BSZ), 256>>>(en, de, nu, out);
}

// round 6
// speedup vs baseline: 1.2125x; 1.2125x over previous
#include <cuda_runtime.h>

// Problem shapes (fixed by the dataset)
#define BSZ  8
#define ENL  512   // encoder length
#define DEL  64    // decoder length
#define EDIM 512   // embedding
#define UDIM 512   // units
#define TDIM 100   // topics
#define STRIP 16   // strip depth in fused kernel

// Scratch (no cudaMalloc allowed)
__device__ float g_aeT[BSZ * UDIM * ENL];   // att_en transposed: [b][u][i]  (8 MB)
__device__ float g_c  [BSZ * DEL * UDIM];   // att_de + topic bias: [b][j][u] (1 MB)

typedef unsigned long long ull;

__device__ __forceinline__ float tanh_fast(float x) {
    float y;
    asm("tanh.approx.f32 %0, %1;" : "=f"(y) : "f"(x));
    return y;
}
__device__ __forceinline__ ull pack2(float x, float y) {
    ull r; asm("mov.b64 %0, {%1, %2};" : "=l"(r) : "f"(x), "f"(y)); return r;
}
__device__ __forceinline__ ull fma2(ull a, ull b, ull c) {
    ull d; asm("fma.rn.f32x2 %0, %1, %2, %3;" : "=l"(d) : "l"(a), "l"(b), "l"(c));
    return d;
}

// ---------------------------------------------------------------------------
// Kernel 1: g_aeT[b][u][i] = sum_e en[b][i][e] * w_en[e][u]
// 64(i) x 128(u) tile, BK=16, 256 threads, 8(u)x4(i) microtile, f32x2 FMAs,
// double-buffered smem with register prefetch. grid = 8x4x8 = 256 blocks.
// ---------------------------------------------------------------------------
__global__ void __launch_bounds__(256, 2) k_gemm_aeT(
    const float* __restrict__ en, const float* __restrict__ w_en)
{
    const int b  = blockIdx.z;
    const int u0 = blockIdx.y * 128;
    const int i0 = blockIdx.x * 64;

    __shared__ float As[2][16][128];  // [e][u] (reads broadcast across warp)
    __shared__ float Bs[2][16][68];   // [e][i] (padded)

    const int tid = threadIdx.x;
    const int tx = tid & 15;          // i micro index (4 i's)
    const int ty = tid >> 4;          // u micro index (8 u's)

    const int ua = tid & 127;
    const int ea = tid >> 7;
    const int eb = tid & 15;
    const int ib = tid >> 4;

    const float* pa = w_en + (size_t)ea * UDIM + u0 + ua;
    const float* pb = en + (size_t)b * ENL * EDIM + (size_t)(i0 + ib) * EDIM + eb;

    ull acc[8][2] = {};

    #pragma unroll
    for (int p = 0; p < 8; p++)
        As[0][ea + 2 * p][ua] = pa[(size_t)(2 * p) * UDIM];
    #pragma unroll
    for (int p = 0; p < 4; p++)
        Bs[0][eb][ib + 16 * p] = pb[(size_t)(16 * p) * EDIM];
    __syncthreads();

    int s = 0;
    for (int t = 0; t < 32; t++) {
        float ra[8], rb[4];
        if (t < 31) {
            const float* qa = pa + (size_t)(t + 1) * 16 * UDIM;
            const float* qb = pb + (t + 1) * 16;
            #pragma unroll
            for (int p = 0; p < 8; p++) ra[p] = qa[(size_t)(2 * p) * UDIM];
            #pragma unroll
            for (int p = 0; p < 4; p++) rb[p] = qb[(size_t)(16 * p) * EDIM];
        }
        #pragma unroll
        for (int k = 0; k < 16; k++) {
            const float4 a0 = *(const float4*)&As[s][k][ty * 8];
            const float4 a1 = *(const float4*)&As[s][k][ty * 8 + 4];
            const ull b01 = *(const ull*)&Bs[s][k][tx * 4];
            const ull b23 = *(const ull*)&Bs[s][k][tx * 4 + 2];
            ull p0 = pack2(a0.x, a0.x), p1 = pack2(a0.y, a0.y);
            ull p2 = pack2(a0.z, a0.z), p3 = pack2(a0.w, a0.w);
            ull p4 = pack2(a1.x, a1.x), p5 = pack2(a1.y, a1.y);
            ull p6 = pack2(a1.z, a1.z), p7 = pack2(a1.w, a1.w);
            acc[0][0]=fma2(p0,b01,acc[0][0]); acc[0][1]=fma2(p0,b23,acc[0][1]);
            acc[1][0]=fma2(p1,b01,acc[1][0]); acc[1][1]=fma2(p1,b23,acc[1][1]);
            acc[2][0]=fma2(p2,b01,acc[2][0]); acc[2][1]=fma2(p2,b23,acc[2][1]);
            acc[3][0]=fma2(p3,b01,acc[3][0]); acc[3][1]=fma2(p3,b23,acc[3][1]);
            acc[4][0]=fma2(p4,b01,acc[4][0]); acc[4][1]=fma2(p4,b23,acc[4][1]);
            acc[5][0]=fma2(p5,b01,acc[5][0]); acc[5][1]=fma2(p5,b23,acc[5][1]);
            acc[6][0]=fma2(p6,b01,acc[6][0]); acc[6][1]=fma2(p6,b23,acc[6][1]);
            acc[7][0]=fma2(p7,b01,acc[7][0]); acc[7][1]=fma2(p7,b23,acc[7][1]);
        }
        if (t < 31) {
            #pragma unroll
            for (int p = 0; p < 8; p++) As[s ^ 1][ea + 2 * p][ua] = ra[p];
            #pragma unroll
            for (int p = 0; p < 4; p++) Bs[s ^ 1][eb][ib + 16 * p] = rb[p];
        }
        __syncthreads();
        s ^= 1;
    }

    float* outp = g_aeT + (size_t)b * UDIM * ENL
                + (size_t)(u0 + ty * 8) * ENL + i0 + tx * 4;
    #pragma unroll
    for (int q = 0; q < 8; q++) {
        ull* row = (ull*)(outp + (size_t)q * ENL);
        row[0] = acc[q][0]; row[1] = acc[q][1];
    }
}

// ---------------------------------------------------------------------------
// Kernel 2: g_c[b][j][u] = sum_e de[b][j][e] * w_de[e][u] + tw[b][u]
// ---------------------------------------------------------------------------
__global__ void __launch_bounds__(256) k_c(
    const float* __restrict__ de, const float* __restrict__ w_de,
    const float* __restrict__ topics, const float* __restrict__ wt)
{
    const int b  = blockIdx.y;
    const int u0 = blockIdx.x * 64;
    __shared__ float As[16][68];  // [e][j]
    __shared__ float Bs[16][68];  // [e][u]
    __shared__ float tws[64];
    const float* deb = de + (size_t)b * DEL * EDIM;
    const int tid = threadIdx.x;
    const int tj = tid & 15;
    const int tu = tid >> 4;
    ull acc2[4][2] = {};

    if (tid < 64) {
        float acc = 0.f;
        const float* wr = wt + (size_t)(u0 + tid) * TDIM;
        const float* tp = topics + b * TDIM;
        #pragma unroll 4
        for (int t = 0; t < TDIM; t++) acc = fmaf(tp[t], wr[t], acc);
        tws[tid] = acc;
    }

    for (int e0 = 0; e0 < EDIM; e0 += 16) {
        #pragma unroll
        for (int r = 0; r < 4; r++) {
            int l = tid + 256 * r;
            int e = l & 15, j = l >> 4;
            As[e][j] = deb[(size_t)j * EDIM + e0 + e];
        }
        #pragma unroll
        for (int r = 0; r < 4; r++) {
            int l = tid + 256 * r;
            int e = l >> 6, uu = l & 63;
            Bs[e][uu] = w_de[(size_t)(e0 + e) * UDIM + u0 + uu];
        }
        __syncthreads();
        #pragma unroll
        for (int k = 0; k < 16; k++) {
            const float4 av = *(const float4*)&As[k][tj * 4];
            const ull b01 = *(const ull*)&Bs[k][tu * 4];
            const ull b23 = *(const ull*)&Bs[k][tu * 4 + 2];
            ull pa0 = pack2(av.x, av.x), pa1 = pack2(av.y, av.y);
            ull pa2 = pack2(av.z, av.z), pa3 = pack2(av.w, av.w);
            acc2[0][0] = fma2(pa0, b01, acc2[0][0]); acc2[0][1] = fma2(pa0, b23, acc2[0][1]);
            acc2[1][0] = fma2(pa1, b01, acc2[1][0]); acc2[1][1] = fma2(pa1, b23, acc2[1][1]);
            acc2[2][0] = fma2(pa2, b01, acc2[2][0]); acc2[2][1] = fma2(pa2, b23, acc2[2][1]);
            acc2[3][0] = fma2(pa3, b01, acc2[3][0]); acc2[3][1] = fma2(pa3, b23, acc2[3][1]);
        }
        __syncthreads();
    }
    #pragma unroll
    for (int r = 0; r < 4; r++) {
        float2 v01, v23;
        asm("mov.b64 {%0, %1}, %2;" : "=f"(v01.x), "=f"(v01.y) : "l"(acc2[r][0]));
        asm("mov.b64 {%0, %1}, %2;" : "=f"(v23.x), "=f"(v23.y) : "l"(acc2[r][1]));
        int j = tj * 4 + r;
        float* row = g_c + ((size_t)b * DEL + j) * UDIM + u0 + tu * 4;
        row[0] = v01.x + tws[tu * 4 + 0];
        row[1] = v01.y + tws[tu * 4 + 1];
        row[2] = v23.x + tws[tu * 4 + 2];
        row[3] = v23.y + tws[tu * 4 + 3];
    }
}

// ---------------------------------------------------------------------------
// Kernel 3 (fused attention): block = (b, j0..j0+1), 512 threads,
// register double-buffered strips so LDG latency hides under MUFU work.
// ---------------------------------------------------------------------------
__global__ void __launch_bounds__(512) k_attn(
    const float* __restrict__ en, const float* __restrict__ de,
    const float* __restrict__ nu, float* __restrict__ out)
{
    const int b  = blockIdx.y;
    const int j0 = blockIdx.x * 2;
    const int t  = threadIdx.x;

    __shared__ float4 css[UDIM];   // (c[j0][u], c[j0+1][u], nu[u], 0)
    __shared__ float2 red2[16];
    __shared__ float2 alph[ENL];

    const float* cb = g_c + ((size_t)b * DEL + j0) * UDIM;
    css[t] = make_float4(cb[t], cb[UDIM + t], nu[t], 0.f);
    __syncthreads();

    // Phase 1: mu for i = t, 2 j's. Software-pipelined strips.
    const float* ae = g_aeT + (size_t)b * UDIM * ENL + t;
    float m0 = 0.f, m1 = 0.f;
    {
        float bufA[STRIP], bufB[STRIP];
        #pragma unroll
        for (int k = 0; k < STRIP; k++)
            bufA[k] = __ldg(ae + (size_t)k * ENL);

        #pragma unroll 1
        for (int u0 = 0; u0 < UDIM; u0 += 2 * STRIP) {
            // prefetch strip u0+STRIP into bufB
            #pragma unroll
            for (int k = 0; k < STRIP; k++)
                bufB[k] = __ldg(ae + (size_t)(u0 + STRIP + k) * ENL);
            // consume bufA (strip u0)
            #pragma unroll
            for (int k = 0; k < STRIP; k++) {
                float4 c4 = css[u0 + k];
                m0 = fmaf(c4.z, tanh_fast(bufA[k] + c4.x), m0);
                m1 = fmaf(c4.z, tanh_fast(bufA[k] + c4.y), m1);
            }
            // prefetch strip u0+2*STRIP into bufA (skip past end)
            if (u0 + 2 * STRIP < UDIM) {
                #pragma unroll
                for (int k = 0; k < STRIP; k++)
                    bufA[k] = __ldg(ae + (size_t)(u0 + 2 * STRIP + k) * ENL);
            }
            // consume bufB (strip u0+STRIP)
            #pragma unroll
            for (int k = 0; k < STRIP; k++) {
                float4 c4 = css[u0 + STRIP + k];
                m0 = fmaf(c4.z, tanh_fast(bufB[k] + c4.x), m0);
                m1 = fmaf(c4.z, tanh_fast(bufB[k] + c4.y), m1);
            }
        }
    }

    const int wid = t >> 5, lane = t & 31;

    float2 r = make_float2(m0, m1);
    #pragma unroll
    for (int o = 16; o; o >>= 1) {
        r.x = fmaxf(r.x, __shfl_xor_sync(0xffffffffu, r.x, o));
        r.y = fmaxf(r.y, __shfl_xor_sync(0xffffffffu, r.y, o));
    }
    if (lane == 0) red2[wid] = r;
    __syncthreads();
    float2 M = red2[0];
    #pragma unroll
    for (int w = 1; w < 16; w++) {
        float2 q = red2[w];
        M.x = fmaxf(M.x, q.x); M.y = fmaxf(M.y, q.y);
    }
    __syncthreads();

    float e0 = __expf(m0 - M.x);
    float e1 = __expf(m1 - M.y);

    float2 s = make_float2(e0, e1);
    #pragma unroll
    for (int o = 16; o; o >>= 1) {
        s.x += __shfl_xor_sync(0xffffffffu, s.x, o);
        s.y += __shfl_xor_sync(0xffffffffu, s.y, o);
    }
    if (lane == 0) red2[wid] = s;
    __syncthreads();
    float2 S = red2[0];
    #pragma unroll
    for (int w = 1; w < 16; w++) {
        float2 q = red2[w];
        S.x += q.x; S.y += q.y;
    }

    float a0 = e0 / S.x, a1 = e1 / S.y;
    alph[t] = make_float2(a0, a1);

    float* alphas_out = out + BSZ * DEL * ENL;
    float* pgen_out   = out + 2 * BSZ * DEL * ENL;
    const int base = ((b * DEL + j0) * ENL) + t;
    alphas_out[base      ] = a0;
    alphas_out[base + ENL] = a1;
    pgen_out[base      ] = 1.f / (1.f + __expf(-m0));
    pgen_out[base + ENL] = 1.f / (1.f + __expf(-m1));
    __syncthreads();

    // Phase 2: sum_en[j][e=t] = sum_i alphas[j][i] * en[b][i][e], pipelined.
    float s0 = 0.f, s1 = 0.f;
    const float* enb = en + (size_t)b * ENL * EDIM + t;
    {
        float bufA[STRIP], bufB[STRIP];
        #pragma unroll
        for (int k = 0; k < STRIP; k++)
            bufA[k] = __ldg(enb + (size_t)k * EDIM);

        #pragma unroll 1
        for (int i0 = 0; i0 < ENL; i0 += 2 * STRIP) {
            #pragma unroll
            for (int k = 0; k < STRIP; k++)
                bufB[k] = __ldg(enb + (size_t)(i0 + STRIP + k) * EDIM);
            #pragma unroll
            for (int k = 0; k < STRIP; k++) {
                float2 av = alph[i0 + k];
                s0 = fmaf(av.x, bufA[k], s0);
                s1 = fmaf(av.y, bufA[k], s1);
            }
            if (i0 + 2 * STRIP < ENL) {
                #pragma unroll
                for (int k = 0; k < STRIP; k++)
                    bufA[k] = __ldg(enb + (size_t)(i0 + 2 * STRIP + k) * EDIM);
            }
            #pragma unroll
            for (int k = 0; k < STRIP; k++) {
                float2 av = alph[i0 + STRIP + k];
                s0 = fmaf(av.x, bufB[k], s0);
                s1 = fmaf(av.y, bufB[k], s1);
            }
        }
    }
    const int ob = ((b * DEL + j0) * EDIM) + t;
    out[ob       ] = de[ob       ] + s0;
    out[ob + EDIM] = de[ob + EDIM] + s1;
}

// ---------------------------------------------------------------------------
extern "C" void kernel_launch(void* const* d_in, const int* in_sizes, int n_in,
                              void* d_out, int out_size)
{
    const float* en     = (const float*)d_in[0];
    const float* de     = (const float*)d_in[1];
    const float* topics = (const float*)d_in[2];
    const float* w_en   = (const float*)d_in[3];
    const float* w_de   = (const float*)d_in[4];
    const float* nu     = (const float*)d_in[5];
    const float* wt     = (const float*)d_in[6];
    float* out = (float*)d_out;

    k_gemm_aeT<<<dim3(ENL / 64, UDIM / 128, BSZ), 256>>>(en, w_en);
    k_c<<<dim3(UDIM / 64, BSZ), 256>>>(de, w_de, topics, wt);
    k_attn<<<dim3(DEL / 2, BSZ), 512>>>(en, de, nu, out);
}